// round 6
// baseline (speedup 1.0000x reference)
#include <cuda_runtime.h>
#include <cstdint>

// ---------------------------------------------------------------------------
// B-spline basis (cubic, DF=16) via de Boor's algorithm.
// KNOTS = [0,0,0] ++ linspace(0, 1+1e-7, 14) ++ [1,1,1]   (fp32, numpy-exact)
// vs R5: smem tile uses dense row stride 16 (smem layout == output layout),
// so the per-thread LDS/STG copy-out is replaced by ONE bulk async TMA store
// (cp.async.bulk.global.shared::cta) of the 16KB tile, double-buffered so the
// next tile's scatter overlaps the in-flight store. Removes all LDS + STG
// wavefronts from the warp issue stream (L1 pipe was at 78%).
// ---------------------------------------------------------------------------

#define STEP_D (1.0000001 / 13.0)
#define KP(i)  ((float)((double)(i) * STEP_D))

__constant__ float KN[20] = {
    0.0f, 0.0f, 0.0f,
    0.0f,                                   // KN[3]  = linspace[0]
    KP(1),  KP(2),  KP(3),  KP(4),  KP(5),  KP(6),
    KP(7),  KP(8),  KP(9),  KP(10), KP(11), KP(12),
    (float)1.0000001,                       // KN[16] = linspace endpoint (exact stop)
    1.0f, 1.0f, 1.0f
};

#define INV_H ((float)(13.0 / 1.0000001))

#define TPB   256
#define TILES 16                    // elements per block = 4096
#define BUFW  (TPB * 16)            // floats per buffer (dense: stride 16)

// One tile: compute + scatter into buf, then kick an async bulk store.
__device__ __forceinline__ float tile_body(
    const float* __restrict__ ts, float* __restrict__ outf,
    const float* sKN, float* buf, int& pj,
    long long base, int k, int n, float t, int tid)
{
    // ---- de Boor: 4 nonzero cubic basis functions, span j in [0,12] ----
    int j = (int)(t * INV_H);
    j = max(0, min(12, j));
    j -= (j > 0)  && (t <  sKN[3 + j]);
    j += (j < 12) && (t >= sKN[4 + j]);

    const int span = j + 3;
    const float l1 = t - sKN[span];
    const float l2 = t - sKN[span - 1];
    const float l3 = t - sKN[span - 2];
    const float r1 = sKN[span + 1] - t;
    const float r2 = sKN[span + 2] - t;
    const float r3 = sKN[span + 3] - t;

    float N0 = 1.0f, N1, N2, N3, sv, tp;
    tp = __fdividef(N0, r1 + l1); N0 = r1 * tp; N1 = l1 * tp;
    tp = __fdividef(N0, r1 + l2); N0 = r1 * tp; sv = l2 * tp;
    tp = __fdividef(N1, r2 + l1); N1 = sv + r2 * tp; N2 = l1 * tp;
    tp = __fdividef(N0, r1 + l3); N0 = r1 * tp; sv = l3 * tp;
    tp = __fdividef(N1, r2 + l2); N1 = sv + r2 * tp; sv = l2 * tp;
    tp = __fdividef(N2, r3 + l1); N2 = sv + r3 * tp; N3 = l1 * tp;

    // Prefetch next tile's t (overlaps with barrier + store issue).
    float tn = 0.0f;
    if (k + 1 < TILES) {
        long long gn = base + (long long)(k + 1) * TPB + tid;
        tn = ts[(gn < n) ? gn : (n - 1)];
    }

    // Zero previously-scattered cells, then scatter the 4 new nonzeros.
    float* row = buf + tid * 16;
    row[pj] = 0.f; row[pj + 1] = 0.f; row[pj + 2] = 0.f; row[pj + 3] = 0.f;
    row[j] = N0; row[j + 1] = N1; row[j + 2] = N2; row[j + 3] = N3;
    pj = j;

    __syncthreads();   // tile fully scattered

    const long long tbase = base + (long long)k * TPB;   // first element of tile
    if (tbase + TPB <= n) {
        if (tid == 0) {
            asm volatile("fence.proxy.async.shared::cta;" ::: "memory");
            uint32_t sa = (uint32_t)__cvta_generic_to_shared(buf);
            asm volatile(
                "cp.async.bulk.global.shared::cta.bulk_group [%0], [%1], %2;"
                :: "l"(outf + tbase * 16), "r"(sa), "r"((int)(BUFW * 4))
                : "memory");
            asm volatile("cp.async.bulk.commit_group;" ::: "memory");
        }
    } else {
        // Rare partial tile: guarded direct copy (smem layout == output layout).
        float4* ob = (float4*)(outf + tbase * 16);
        const long long lim4 = (long long)n * 4 - tbase * 4;
        #pragma unroll
        for (int i = 0; i < 4; i++) {
            int f = tid + TPB * i;
            if (f < lim4) ob[f] = ((float4*)buf)[f];
        }
    }
    return tn;
}

__global__ __launch_bounds__(TPB) void bspline_kernel(
    const float* __restrict__ ts,
    float* __restrict__ outf,
    int n)
{
    __shared__ float sKN[20];
    __shared__ __align__(128) float sB0[BUFW];
    __shared__ __align__(128) float sB1[BUFW];

    const int tid = threadIdx.x;
    if (tid < 20) sKN[tid] = KN[tid];

    // Zero this thread's row in both buffers; pj starts at 0 (re-zero of [0..3]
    // on the first visit is harmless).
    float4* r0 = (float4*)(sB0 + tid * 16);
    float4* r1 = (float4*)(sB1 + tid * 16);
    #pragma unroll
    for (int i = 0; i < 4; i++) {
        r0[i] = make_float4(0.f, 0.f, 0.f, 0.f);
        r1[i] = make_float4(0.f, 0.f, 0.f, 0.f);
    }
    int pj0 = 0, pj1 = 0;

    const long long base = (long long)blockIdx.x * (TPB * TILES);
    long long gi = base + tid;
    float t = ts[(gi < n) ? gi : (n - 1)];

    __syncthreads();   // knots + zero-fill visible

    #pragma unroll 1
    for (int k = 0; k < TILES; k += 2) {
        // Recycle buffer 0: wait until at most 1 bulk group pending
        // (i.e. the store issued from sB0 two tiles ago has finished reading).
        if (tid == 0) asm volatile("cp.async.bulk.wait_group.read 1;" ::: "memory");
        __syncthreads();
        t = tile_body(ts, outf, sKN, sB0, pj0, base, k,     n, t, tid);

        // Recycle buffer 1.
        if (tid == 0) asm volatile("cp.async.bulk.wait_group.read 1;" ::: "memory");
        __syncthreads();
        t = tile_body(ts, outf, sKN, sB1, pj1, base, k + 1, n, t, tid);
    }

    // Drain all pending bulk stores before exit.
    if (tid == 0) asm volatile("cp.async.bulk.wait_group 0;" ::: "memory");
}

extern "C" void kernel_launch(void* const* d_in, const int* in_sizes, int n_in,
                              void* d_out, int out_size)
{
    const float* ts = (const float*)d_in[0];
    float* outf = (float*)d_out;
    const int n = in_sizes[0];           // 32 * 131072 = 4194304 elements
    const int epb = TPB * TILES;         // 4096 elements per block
    const int blocks = (n + epb - 1) / epb;
    bspline_kernel<<<blocks, TPB>>>(ts, outf, n);
}

// round 8
// speedup vs baseline: 1.0746x; 1.0746x over previous
#include <cuda_runtime.h>
#include <cstdint>

// ---------------------------------------------------------------------------
// B-spline basis (cubic, DF=16) via de Boor's algorithm.
// KNOTS = [0,0,0] ++ linspace(0, 1+1e-7, 14) ++ [1,1,1]   (fp32, numpy-exact)
// vs R6: persistent residency-sized grid (148 SMs x 6 CTAs @ 33KB smem) with
// grid-stride over 256-element tiles — kills the ragged second wave that sank
// R6 (grid 1024 vs 888 resident). TMA bulk store path kept: dense stride-16
// smem tile == output layout, one cp.async.bulk per tile, double-buffered,
// wait_group.read 1 keeps two stores in flight per CTA.
// ---------------------------------------------------------------------------

#define STEP_D (1.0000001 / 13.0)
#define KP(i)  ((float)((double)(i) * STEP_D))

__constant__ float KN[20] = {
    0.0f, 0.0f, 0.0f,
    0.0f,                                   // KN[3]  = linspace[0]
    KP(1),  KP(2),  KP(3),  KP(4),  KP(5),  KP(6),
    KP(7),  KP(8),  KP(9),  KP(10), KP(11), KP(12),
    (float)1.0000001,                       // KN[16] = linspace endpoint (exact stop)
    1.0f, 1.0f, 1.0f
};

#define INV_H ((float)(13.0 / 1.0000001))

#define TPB   256
#define BUFW  (TPB * 16)            // floats per buffer (dense: stride 16)
#define NSM   148
#define CPSM  6                     // CTAs/SM at 33KB smem

__global__ __launch_bounds__(TPB) void bspline_kernel(
    const float* __restrict__ ts,
    float* __restrict__ outf,
    int n)
{
    __shared__ float sKN[20];
    __shared__ __align__(128) float sB0[BUFW];
    __shared__ __align__(128) float sB1[BUFW];

    const int tid = threadIdx.x;
    const int G   = gridDim.x;
    const int nt  = (n + TPB - 1) / TPB;    // number of 256-element tiles

    if (tid < 20) sKN[tid] = KN[tid];

    // Zero this thread's row in both buffers.
    {
        float4 z = make_float4(0.f, 0.f, 0.f, 0.f);
        float4* r0 = (float4*)(sB0 + tid * 16);
        float4* r1 = (float4*)(sB1 + tid * 16);
        #pragma unroll
        for (int i = 0; i < 4; i++) { r0[i] = z; r1[i] = z; }
    }
    int pj0 = 0, pj1 = 0;
    int parity = 0;

    // Prefetch first tile's t.
    int tile = blockIdx.x;
    float t = 0.0f;
    if (tile < nt) {
        long long gi = (long long)tile * TPB + tid;
        t = ts[(gi < n) ? gi : (n - 1)];
    }

    __syncthreads();   // knots + zero-fill visible

    #pragma unroll 1
    for (; tile < nt; tile += G) {
        float* buf = parity ? sB1 : sB0;
        int    pj  = parity ? pj1 : pj0;

        // Recycle this buffer: its previous store (2 commits ago) must be done.
        if (tid == 0) asm volatile("cp.async.bulk.wait_group.read 1;" ::: "memory");

        // ---- de Boor: 4 nonzero cubic basis functions, span j in [0,12] ----
        int j = (int)(t * INV_H);
        j = max(0, min(12, j));
        j -= (j > 0)  && (t <  sKN[3 + j]);
        j += (j < 12) && (t >= sKN[4 + j]);

        const int span = j + 3;
        const float l1 = t - sKN[span];
        const float l2 = t - sKN[span - 1];
        const float l3 = t - sKN[span - 2];
        const float r1 = sKN[span + 1] - t;
        const float r2 = sKN[span + 2] - t;
        const float r3 = sKN[span + 3] - t;

        float N0 = 1.0f, N1, N2, N3, sv, tp;
        tp = __fdividef(N0, r1 + l1); N0 = r1 * tp; N1 = l1 * tp;
        tp = __fdividef(N0, r1 + l2); N0 = r1 * tp; sv = l2 * tp;
        tp = __fdividef(N1, r2 + l1); N1 = sv + r2 * tp; N2 = l1 * tp;
        tp = __fdividef(N0, r1 + l3); N0 = r1 * tp; sv = l3 * tp;
        tp = __fdividef(N1, r2 + l2); N1 = sv + r2 * tp; sv = l2 * tp;
        tp = __fdividef(N2, r3 + l1); N2 = sv + r3 * tp; N3 = l1 * tp;

        // Prefetch next tile's t (overlaps barriers + store issue).
        float tn = 0.0f;
        if (tile + G < nt) {
            long long gn = (long long)(tile + G) * TPB + tid;
            tn = ts[(gn < n) ? gn : (n - 1)];
        }

        __syncthreads();   // buffer recycled (tid0's wait done), safe to write

        // Zero previously-scattered cells, then scatter the 4 new nonzeros.
        float* row = buf + tid * 16;
        row[pj] = 0.f; row[pj + 1] = 0.f; row[pj + 2] = 0.f; row[pj + 3] = 0.f;
        row[j] = N0; row[j + 1] = N1; row[j + 2] = N2; row[j + 3] = N3;
        if (parity) pj1 = j; else pj0 = j;

        __syncthreads();   // tile fully scattered

        const long long tbase = (long long)tile * TPB;
        if (tbase + TPB <= n) {
            if (tid == 0) {
                asm volatile("fence.proxy.async.shared::cta;" ::: "memory");
                uint32_t sa = (uint32_t)__cvta_generic_to_shared(buf);
                asm volatile(
                    "cp.async.bulk.global.shared::cta.bulk_group [%0], [%1], %2;"
                    :: "l"(outf + tbase * 16), "r"(sa), "r"((int)(BUFW * 4))
                    : "memory");
                asm volatile("cp.async.bulk.commit_group;" ::: "memory");
            }
        } else {
            // Partial tile: guarded direct copy (smem layout == output layout).
            float4* ob = (float4*)(outf + tbase * 16);
            const long long lim4 = (long long)n * 4 - tbase * 4;
            #pragma unroll
            for (int i = 0; i < 4; i++) {
                int f = tid + TPB * i;
                if (f < lim4) ob[f] = ((float4*)buf)[f];
            }
        }

        parity ^= 1;
        t = tn;
    }

    // Drain all pending bulk stores before exit.
    if (tid == 0) asm volatile("cp.async.bulk.wait_group 0;" ::: "memory");
}

extern "C" void kernel_launch(void* const* d_in, const int* in_sizes, int n_in,
                              void* d_out, int out_size)
{
    const float* ts = (const float*)d_in[0];
    float* outf = (float*)d_out;
    const int n = in_sizes[0];           // 32 * 131072 = 4194304 elements
    const int nt = (n + TPB - 1) / TPB;  // 16384 tiles
    int blocks = NSM * CPSM;             // residency-sized persistent grid
    if (blocks > nt) blocks = nt;
    bspline_kernel<<<blocks, TPB>>>(ts, outf, n);
}